// round 15
// baseline (speedup 1.0000x reference)
#include <cuda_runtime.h>
#include <cuda_fp16.h>
#include <stdint.h>

#define TT     365
#define NTHR   512
#define MR     64            // batch rows per cluster (and per CTA)
#define KSTEPS 18
#define LDA    296           // A row stride (halfs)
#define GLD4   516           // gates row stride (floats)
#define SMEM_A (MR * LDA * 2)                   // 37888 per buffer
#define SMEM_BYTES (2 * SMEM_A + MR * GLD4 * 4) // 207872

// Per-rank fragment-order weights: ntile = warp*4 + gate; col-in-tile = unit%8.
// [rank][ks][ntile 0..63][lane] -> uint2 (mma B fragment, proven mapping)
__device__ uint2 g_W[2][KSTEPS * 64 * 32];

__global__ void lstm_prep_kernel(const float* __restrict__ w_ih,
                                 const float* __restrict__ w_hh) {
    int g = blockIdx.x * blockDim.x + threadIdx.x;
    if (g >= 2 * KSTEPS * 64 * 32) return;
    int rank = g / (KSTEPS * 64 * 32), rem = g % (KSTEPS * 64 * 32);
    int lane = rem & 31, ntile = (rem >> 5) & 63, ks = rem >> 11;
    int w = ntile >> 2, q = ntile & 3;
    int ng = q * 256 + rank * 128 + w * 8 + (lane >> 2);
    int kb = ks * 16 + 2 * (lane & 3);
    float v[4];
    int ko[4] = {kb, kb + 1, kb + 8, kb + 9};
#pragma unroll
    for (int u = 0; u < 4; u++) {
        int k = ko[u];
        v[u] = (k < 256) ? w_hh[ng * 256 + k] : w_ih[ng * 32 + (k - 256)];
    }
    uint2 val;
    val.x = ((unsigned)__half_as_ushort(__float2half(v[1])) << 16)
          |  (unsigned)__half_as_ushort(__float2half(v[0]));
    val.y = ((unsigned)__half_as_ushort(__float2half(v[3])) << 16)
          |  (unsigned)__half_as_ushort(__float2half(v[2]));
    g_W[rank][rem] = val;
}

__device__ __forceinline__ unsigned su32(const void* p) {
    return (unsigned)__cvta_generic_to_shared(p);
}
__device__ __forceinline__ unsigned ctarank() {
    unsigned r; asm("mov.u32 %0, %%cluster_ctarank;" : "=r"(r)); return r;
}
__device__ __forceinline__ void csync() {
    asm volatile("barrier.cluster.arrive.aligned;" ::: "memory");
    asm volatile("barrier.cluster.wait.aligned;" ::: "memory");
}
__device__ __forceinline__ unsigned mapa_u32(unsigned a, unsigned cta) {
    unsigned r;
    asm("mapa.shared::cluster.u32 %0, %1, %2;" : "=r"(r) : "r"(a), "r"(cta));
    return r;
}
__device__ __forceinline__ void st_remote(unsigned a, unsigned v) {
    asm volatile("st.shared::cluster.u32 [%0], %1;" :: "r"(a), "r"(v) : "memory");
}
__device__ __forceinline__ void ldmatrix_x4(unsigned a, unsigned& r0, unsigned& r1,
                                            unsigned& r2, unsigned& r3) {
    asm volatile("ldmatrix.sync.aligned.m8n8.x4.shared.b16 {%0,%1,%2,%3}, [%4];\n"
                 : "=r"(r0), "=r"(r1), "=r"(r2), "=r"(r3) : "r"(a));
}
__device__ __forceinline__ void mma16816(float* c, unsigned a0, unsigned a1,
                                         unsigned a2, unsigned a3,
                                         unsigned b0, unsigned b1) {
    asm volatile(
        "mma.sync.aligned.m16n8k16.row.col.f32.f16.f16.f32 "
        "{%0,%1,%2,%3}, {%4,%5,%6,%7}, {%8,%9}, {%0,%1,%2,%3};\n"
        : "+f"(c[0]), "+f"(c[1]), "+f"(c[2]), "+f"(c[3])
        : "r"(a0), "r"(a1), "r"(a2), "r"(a3), "r"(b0), "r"(b1));
}
__device__ __forceinline__ float tanha(float x) {
    float r; asm("tanh.approx.f32 %0, %1;" : "=f"(r) : "f"(x)); return r;
}
__device__ __forceinline__ float cellh(float pi, float pf, float pg, float po,
                                       float& c) {
    float ig = 0.5f * tanha(0.5f * pi) + 0.5f;
    float fg = 0.5f * tanha(0.5f * pf) + 0.5f;
    float og = 0.5f * tanha(0.5f * po) + 0.5f;
    c = fg * c + ig * tanha(pg);
    return og * tanha(c);
}

__global__ void __launch_bounds__(NTHR, 1) __cluster_dims__(2, 1, 1)
lstm_main_kernel(const float* __restrict__ xd,
                 const float* __restrict__ b,
                 const float* __restrict__ w_out,
                 const float* __restrict__ b_out,
                 float* __restrict__ out) {
    extern __shared__ char smem[];
    float* gates = (float*)(smem + 2 * SMEM_A);     // [64][GLD4] warp-private cols

    const int tid = threadIdx.x, lane = tid & 31, warp = tid >> 5;
    const int rank = (int)ctarank();
    const int rowbase = (blockIdx.x >> 1) * MR;
    const unsigned peer = (unsigned)(rank ^ 1);

    const int lrow = lane & 7, lsel = lane >> 3;
    const int aRowOff = lrow + ((lsel & 1) << 3);
    const int aColOff = (lsel >> 1) << 3;
    const int cRow = lane >> 2, cCol = (lane & 3) * 2;

    // cells: 2 adjacent units, rows rg+8k
    const int ulocal = (lane & 3) * 2;              // 0,2,4,6
    const int ucol = warp * 8 + ulocal;             // local unit col 0..127
    const int rg = lane >> 2;                       // 0..7
    const int ugl = rank * 128 + ucol;              // global unit

    float bia[2][4];
#pragma unroll
    for (int du = 0; du < 2; du++)
#pragma unroll
        for (int q = 0; q < 4; q++) bia[du][q] = b[q * 256 + ugl + du];

    float c_reg[16];
#pragma unroll
    for (int k = 0; k < 16; k++) c_reg[k] = 0.f;

    // zero h-part of buffer 0 only (buffer 1 h fully overwritten by pushes)
    for (int idx = tid; idx < MR * 128; idx += NTHR) {
        int r = idx >> 7, c2 = idx & 127;
        ((__half2*)smem)[r * (LDA / 2) + c2] = __half2half2(__float2half(0.f));
    }
    // stage x_0 into buffer 0
#pragma unroll
    for (int u = 0; u < 2; u++) {
        int idx = tid + u * NTHR;                   // 0..1023
        int row = idx >> 4, i2 = idx & 15;
        float2 v = __ldcs((const float2*)(xd + (size_t)(rowbase + row) * (TT * 32)) + i2);
        ((__half2*)((__half*)smem + row * LDA + 256))[i2] = __floats2half2_rn(v.x, v.y);
    }
    __syncthreads();
    csync();

    const uint2* wrank = g_W[rank];

    for (int t = 0; t < TT; t++) {
        __half* Acur = (__half*)(smem + (t & 1) * SMEM_A);
        __half* Anxt = (__half*)(smem + ((t + 1) & 1) * SMEM_A);

        // ---- GEMM: warp -> M=64 x 32 cols (units warp*8..+7, 4 gates) ----
        float acc[4][4][4];
#pragma unroll
        for (int mt = 0; mt < 4; mt++)
#pragma unroll
            for (int q = 0; q < 4; q++)
#pragma unroll
                for (int u = 0; u < 4; u++) acc[mt][q][u] = 0.f;

#pragma unroll
        for (int ks = 0; ks < KSTEPS; ks++) {
            unsigned a[4][4];
#pragma unroll
            for (int mt = 0; mt < 4; mt++) {
                const __half* p = Acur + (mt * 16 + aRowOff) * LDA + ks * 16 + aColOff;
                ldmatrix_x4(su32(p), a[mt][0], a[mt][1], a[mt][2], a[mt][3]);
            }
            const uint2* wp = wrank + (ks * 64 + warp * 4) * 32 + lane;
#pragma unroll
            for (int q = 0; q < 4; q++) {
                uint2 bb = __ldcg(wp + q * 32);
#pragma unroll
                for (int mt = 0; mt < 4; mt++)
                    mma16816(acc[mt][q], a[mt][0], a[mt][1], a[mt][2], a[mt][3],
                             bb.x, bb.y);
            }
        }

        // early x(t+1) loads
        float2 xv[2];
        if (t + 1 < TT) {
#pragma unroll
            for (int u = 0; u < 2; u++) {
                int idx = tid + u * NTHR;
                int row = idx >> 4, i2 = idx & 15;
                xv[u] = __ldcs((const float2*)(xd + (size_t)(rowbase + row) * (TT * 32)
                                               + (size_t)(t + 1) * 32) + i2);
            }
        }

        // ---- writeback: float4 {i,f,g,o} per (row, unit) ----
#pragma unroll
        for (int mt = 0; mt < 4; mt++)
#pragma unroll
            for (int rr = 0; rr < 2; rr++)
#pragma unroll
                for (int cc = 0; cc < 2; cc++) {
                    int row = mt * 16 + cRow + rr * 8;
                    int u = warp * 8 + cCol + cc;
                    int fu = rr * 2 + cc;
                    *(float4*)&gates[row * GLD4 + u * 4] =
                        make_float4(acc[mt][0][fu], acc[mt][1][fu],
                                    acc[mt][2][fu], acc[mt][3][fu]);
                }
        __syncwarp();

        // ---- cells + DSMEM push (units ucol, ucol+1; rows rg+8k) ----
        unsigned lbase = su32(Anxt) + (unsigned)(rg * LDA + ugl) * 2u;
        unsigned rbase = mapa_u32(lbase, peer);
#pragma unroll
        for (int k = 0; k < 8; k++) {
            int row = rg + 8 * k;
            float4 ga = *(const float4*)&gates[row * GLD4 + ucol * 4];
            float4 gb = *(const float4*)&gates[row * GLD4 + (ucol + 1) * 4];
            float h0 = cellh(ga.x + bia[0][0], ga.y + bia[0][1],
                             ga.z + bia[0][2], ga.w + bia[0][3], c_reg[2 * k]);
            float h1 = cellh(gb.x + bia[1][0], gb.y + bia[1][1],
                             gb.z + bia[1][2], gb.w + bia[1][3], c_reg[2 * k + 1]);
            __half2 hp = __floats2half2_rn(h0, h1);
            unsigned v = __half2_raw(hp).x | ((unsigned)__half2_raw(hp).y << 16);
            unsigned off = (unsigned)(k * 8 * LDA) * 2u;
            asm volatile("st.shared.u32 [%0], %1;" :: "r"(lbase + off), "r"(v) : "memory");
            st_remote(rbase + off, v);
        }
        if (t + 1 < TT) {
#pragma unroll
            for (int u = 0; u < 2; u++) {
                int idx = tid + u * NTHR;
                int row = idx >> 4, i2 = idx & 15;
                ((__half2*)(Anxt + row * LDA + 256))[i2] =
                    __floats2half2_rn(xv[u].x, xv[u].y);
            }
        }
        csync();   // h exchange + x staging visible cluster-wide
    }

    // ---- output: rank handles rows rank*32..+31 ----
    __half* Afin = (__half*)(smem + (TT & 1) * SMEM_A);
    {
        int rloc = rank * 32 + (tid >> 4);          // local row 0..63
        int seg = tid & 15;
        float s = 0.f;
#pragma unroll
        for (int u = 0; u < 16; u++) {
            int uu = seg * 16 + u;
            s += __half2float(Afin[rloc * LDA + uu]) * w_out[uu];
        }
        gates[(tid >> 4) * 20 + seg] = s;
    }
    __syncthreads();
    if (tid < 32) {
        float s = b_out[0];
#pragma unroll
        for (int g2 = 0; g2 < 16; g2++) s += gates[tid * 20 + g2];
        out[rowbase + rank * 32 + tid] = fmaxf(s, 0.f);
    }
    csync();   // keep cluster alive until peers finish reading Afin
}

extern "C" void kernel_launch(void* const* d_in, const int* in_sizes, int n_in,
                              void* d_out, int out_size) {
    const float* xd    = (const float*)d_in[0];
    const float* w_ih  = (const float*)d_in[1];
    const float* w_hh  = (const float*)d_in[2];
    const float* b     = (const float*)d_in[3];
    const float* w_out = (const float*)d_in[4];
    const float* b_out = (const float*)d_in[5];

    cudaFuncSetAttribute(lstm_main_kernel,
                         cudaFuncAttributeMaxDynamicSharedMemorySize, SMEM_BYTES);
    lstm_prep_kernel<<<288, 256>>>(w_ih, w_hh);
    lstm_main_kernel<<<128, NTHR, SMEM_BYTES>>>(xd, b, w_out, b_out, (float*)d_out);
}

// round 16
// speedup vs baseline: 1.1724x; 1.1724x over previous
#include <cuda_runtime.h>
#include <cuda_fp16.h>
#include <stdint.h>

#define TT     365
#define NTHR   512
#define MR     64            // rows per cluster (each CTA computes all 64 rows)
#define KSTEPS 18
#define LDA    296
#define GLD4   516
#define SMEM_A (MR * LDA * 2)                   // 37888 / buffer
#define SMEM_BYTES (2 * SMEM_A + MR * GLD4 * 4) // 207872

// Per-rank fragment-order weights: [(ks*64 + ugrp*8 + nt)*32 + lane]
// nt = gate*2 + su; global gate row = gate*256 + rank*128 + ugrp*16 + su*8 + (lane>>2)
__device__ uint2 g_W[2][KSTEPS * 64 * 32];

__global__ void lstm_prep_kernel(const float* __restrict__ w_ih,
                                 const float* __restrict__ w_hh) {
    int g = blockIdx.x * blockDim.x + threadIdx.x;
    if (g >= 2 * KSTEPS * 64 * 32) return;
    int rank = g / (KSTEPS * 64 * 32), rem = g % (KSTEPS * 64 * 32);
    int lane = rem & 31, ntile = (rem >> 5) & 63, ks = rem >> 11;
    int ugrp = ntile >> 3, nt = ntile & 7;
    int ng = (nt >> 1) * 256 + rank * 128 + ugrp * 16 + (nt & 1) * 8 + (lane >> 2);
    int kb = ks * 16 + 2 * (lane & 3);
    float v[4];
    int ko[4] = {kb, kb + 1, kb + 8, kb + 9};
#pragma unroll
    for (int u = 0; u < 4; u++) {
        int k = ko[u];
        v[u] = (k < 256) ? w_hh[ng * 256 + k] : w_ih[ng * 32 + (k - 256)];
    }
    uint2 val;
    val.x = ((unsigned)__half_as_ushort(__float2half(v[1])) << 16)
          |  (unsigned)__half_as_ushort(__float2half(v[0]));
    val.y = ((unsigned)__half_as_ushort(__float2half(v[3])) << 16)
          |  (unsigned)__half_as_ushort(__float2half(v[2]));
    g_W[rank][rem] = val;
}

__device__ __forceinline__ unsigned su32(const void* p) {
    return (unsigned)__cvta_generic_to_shared(p);
}
__device__ __forceinline__ unsigned ctarank() {
    unsigned r; asm("mov.u32 %0, %%cluster_ctarank;" : "=r"(r)); return r;
}
__device__ __forceinline__ void csync() {
    asm volatile("barrier.cluster.arrive.aligned;" ::: "memory");
    asm volatile("barrier.cluster.wait.aligned;" ::: "memory");
}
__device__ __forceinline__ unsigned mapa_u32(unsigned a, unsigned cta) {
    unsigned r;
    asm("mapa.shared::cluster.u32 %0, %1, %2;" : "=r"(r) : "r"(a), "r"(cta));
    return r;
}
__device__ __forceinline__ void st_remote16(unsigned a, unsigned short v) {
    asm volatile("st.shared::cluster.b16 [%0], %1;" :: "r"(a), "h"(v) : "memory");
}
__device__ __forceinline__ void ldmatrix_x4(unsigned a, unsigned& r0, unsigned& r1,
                                            unsigned& r2, unsigned& r3) {
    asm volatile("ldmatrix.sync.aligned.m8n8.x4.shared.b16 {%0,%1,%2,%3}, [%4];\n"
                 : "=r"(r0), "=r"(r1), "=r"(r2), "=r"(r3) : "r"(a));
}
__device__ __forceinline__ void mma16816(float* c, unsigned a0, unsigned a1,
                                         unsigned a2, unsigned a3,
                                         unsigned b0, unsigned b1) {
    asm volatile(
        "mma.sync.aligned.m16n8k16.row.col.f32.f16.f16.f32 "
        "{%0,%1,%2,%3}, {%4,%5,%6,%7}, {%8,%9}, {%0,%1,%2,%3};\n"
        : "+f"(c[0]), "+f"(c[1]), "+f"(c[2]), "+f"(c[3])
        : "r"(a0), "r"(a1), "r"(a2), "r"(a3), "r"(b0), "r"(b1));
}
__device__ __forceinline__ float tanha(float x) {
    float r; asm("tanh.approx.f32 %0, %1;" : "=f"(r) : "f"(x)); return r;
}
__device__ __forceinline__ float cellh(float pi, float pf, float pg, float po,
                                       float& c) {
    float ig = 0.5f * tanha(0.5f * pi) + 0.5f;
    float fg = 0.5f * tanha(0.5f * pf) + 0.5f;
    float og = 0.5f * tanha(0.5f * po) + 0.5f;
    c = fg * c + ig * tanha(pg);
    return og * tanha(c);
}

__global__ void __launch_bounds__(NTHR, 1) __cluster_dims__(2, 1, 1)
lstm_main_kernel(const float* __restrict__ xd,
                 const float* __restrict__ b,
                 const float* __restrict__ w_out,
                 const float* __restrict__ b_out,
                 float* __restrict__ out) {
    extern __shared__ char smem[];
    float* gates = (float*)(smem + 2 * SMEM_A);   // [64 rows][128 units][4 gates]

    const int tid = threadIdx.x, lane = tid & 31, warp = tid >> 5;
    const int ugrp = warp & 7;                    // unit group 0..7 (16 units)
    const int wrow = warp >> 3;                   // row group 0..1 (32 rows)
    const int rank = (int)ctarank();
    const int rowbase = (blockIdx.x >> 1) * MR;
    const unsigned peer = (unsigned)(rank ^ 1);

    const int lrow = lane & 7, lsel = lane >> 3;
    const int aRowOff = lrow + ((lsel & 1) << 3);
    const int aColOff = (lsel >> 1) << 3;
    const int cRow = lane >> 2, cCol = (lane & 3) * 2;

    // warp-local cells: unit ju (local 0..127), rows wrow*32 + (lane>>4)*16 ..+15
    const int ju  = ugrp * 16 + (lane & 15);
    const int jrb = wrow * 32 + (lane >> 4) * 16;
    const int ugl = rank * 128 + ju;
    const float bi = b[ugl], bf = b[256 + ugl], bg = b[512 + ugl], bo = b[768 + ugl];

    float c_reg[16];
#pragma unroll
    for (int k = 0; k < 16; k++) c_reg[k] = 0.f;

    // zero h-part of buffer 0; stage x_0
    for (int idx = tid; idx < MR * 128; idx += NTHR) {
        int r = idx >> 7, c2 = idx & 127;
        ((__half2*)smem)[r * (LDA / 2) + c2] = __half2half2(__float2half(0.f));
    }
#pragma unroll
    for (int u = 0; u < 2; u++) {
        int idx = tid + u * NTHR;
        int row = idx >> 4, i2 = idx & 15;
        float2 v = __ldcs((const float2*)(xd + (size_t)(rowbase + row) * (TT * 32)) + i2);
        ((__half2*)((__half*)smem + row * LDA + 256))[i2] = __floats2half2_rn(v.x, v.y);
    }
    __syncthreads();
    csync();

    const uint2* __restrict__ wrank = g_W[rank];

    for (int t = 0; t < TT; t++) {
        __half* Acur = (__half*)(smem + (t & 1) * SMEM_A);
        __half* Anxt = (__half*)(smem + ((t + 1) & 1) * SMEM_A);

        // ---- GEMM: warp = rows wrow*32..+31 x 64 cols (units ugrp*16..+15) ----
        float acc[2][8][4];
#pragma unroll
        for (int mt = 0; mt < 2; mt++)
#pragma unroll
            for (int nt = 0; nt < 8; nt++)
#pragma unroll
                for (int u = 0; u < 4; u++) acc[mt][nt][u] = 0.f;

#pragma unroll
        for (int ks = 0; ks < KSTEPS; ks++) {
            unsigned a[2][4];
#pragma unroll
            for (int mt = 0; mt < 2; mt++) {
                const __half* p = Acur + (wrow * 32 + mt * 16 + aRowOff) * LDA
                                + ks * 16 + aColOff;
                ldmatrix_x4(su32(p), a[mt][0], a[mt][1], a[mt][2], a[mt][3]);
            }
            const uint2* wp = wrank + (ks * 64 + ugrp * 8) * 32 + lane;
#pragma unroll
            for (int nt = 0; nt < 8; nt++) {
                uint2 bb = __ldg(wp + nt * 32);   // L1-paired with warp^8
                mma16816(acc[0][nt], a[0][0], a[0][1], a[0][2], a[0][3], bb.x, bb.y);
                mma16816(acc[1][nt], a[1][0], a[1][1], a[1][2], a[1][3], bb.x, bb.y);
            }
        }

        // early x(t+1) loads
        float2 xv[2];
        if (t + 1 < TT) {
#pragma unroll
            for (int u = 0; u < 2; u++) {
                int idx = tid + u * NTHR;
                int row = idx >> 4, i2 = idx & 15;
                xv[u] = __ldcs((const float2*)(xd + (size_t)(rowbase + row) * (TT * 32)
                                               + (size_t)(t + 1) * 32) + i2);
            }
        }

        // ---- writeback: float4 {i,f,g,o} per (row, local unit) ----
#pragma unroll
        for (int mt = 0; mt < 2; mt++)
#pragma unroll
            for (int rr = 0; rr < 2; rr++)
#pragma unroll
                for (int su = 0; su < 2; su++)
#pragma unroll
                    for (int cc = 0; cc < 2; cc++) {
                        int row = wrow * 32 + mt * 16 + cRow + rr * 8;
                        int u = ugrp * 16 + su * 8 + cCol + cc;
                        int fu = rr * 2 + cc;
                        *(float4*)&gates[row * GLD4 + u * 4] =
                            make_float4(acc[mt][0 + su][fu], acc[mt][2 + su][fu],
                                        acc[mt][4 + su][fu], acc[mt][6 + su][fu]);
                    }
        __syncwarp();

        // ---- warp-local cells + local h store + DSMEM push to peer ----
        unsigned lbase = su32(Anxt) + (unsigned)(jrb * LDA + ugl) * 2u;
        unsigned rbase = mapa_u32(lbase, peer);
#pragma unroll
        for (int k = 0; k < 16; k++) {
            int row = jrb + k;
            float4 g4 = *(const float4*)&gates[row * GLD4 + ju * 4];
            float h = cellh(g4.x + bi, g4.y + bf, g4.z + bg, g4.w + bo, c_reg[k]);
            unsigned short hv = (unsigned short)__half_as_ushort(__float2half(h));
            unsigned off = (unsigned)(k * LDA) * 2u;
            asm volatile("st.shared.b16 [%0], %1;" :: "r"(lbase + off), "h"(hv)
                         : "memory");
            st_remote16(rbase + off, hv);
        }
        if (t + 1 < TT) {
#pragma unroll
            for (int u = 0; u < 2; u++) {
                int idx = tid + u * NTHR;
                int row = idx >> 4, i2 = idx & 15;
                ((__half2*)(Anxt + row * LDA + 256))[i2] =
                    __floats2half2_rn(xv[u].x, xv[u].y);
            }
        }
        csync();   // one sync/step: h exchange + x staging visible cluster-wide
    }

    // ---- output: rank handles rows rank*32..+31 ----
    __half* Afin = (__half*)(smem + (TT & 1) * SMEM_A);
    {
        int rloc = rank * 32 + (tid >> 4);
        int seg = tid & 15;
        float s = 0.f;
#pragma unroll
        for (int u = 0; u < 16; u++) {
            int uu = seg * 16 + u;
            s += __half2float(Afin[rloc * LDA + uu]) * w_out[uu];
        }
        gates[(tid >> 4) * 20 + seg] = s;
    }
    __syncthreads();
    if (tid < 32) {
        float s = b_out[0];
#pragma unroll
        for (int g2 = 0; g2 < 16; g2++) s += gates[tid * 20 + g2];
        out[rowbase + rank * 32 + tid] = fmaxf(s, 0.f);
    }
    csync();   // keep cluster alive until peers finish
}

extern "C" void kernel_launch(void* const* d_in, const int* in_sizes, int n_in,
                              void* d_out, int out_size) {
    const float* xd    = (const float*)d_in[0];
    const float* w_ih  = (const float*)d_in[1];
    const float* w_hh  = (const float*)d_in[2];
    const float* b     = (const float*)d_in[3];
    const float* w_out = (const float*)d_in[4];
    const float* b_out = (const float*)d_in[5];

    cudaFuncSetAttribute(lstm_main_kernel,
                         cudaFuncAttributeMaxDynamicSharedMemorySize, SMEM_BYTES);
    lstm_prep_kernel<<<288, 256>>>(w_ih, w_hh);
    lstm_main_kernel<<<128, NTHR, SMEM_BYTES>>>(xd, b, w_out, b_out, (float*)d_out);
}